// round 7
// baseline (speedup 1.0000x reference)
#include <cuda_runtime.h>
#include <cstdint>

// Problem dims
#define BB 8
#define DD 1024
#define TT 8192
#define NCB 9
#define KK 1024
#define NT (BB*TT)        // 65536 tokens
#define CN (NCB*8)        // 72

// Output layout (float32, tuple flattened in order)
#define OFF_CODES ((size_t)BB*DD*TT)                  // 67108864
#define OFF_LAT   (OFF_CODES + (size_t)BB*NCB*TT)     // 67698688
#define OFF_CL    (OFF_LAT + (size_t)BB*CN*TT)        // 72417280

#define THREADS 128
#define GB (NT/THREADS)   // 512 blocks

// Dynamic smem layout (float indices): argmin-hot tables only
#define SM_CB2 0          // 8192: codebook pair-interleaved
#define SM_CC2 8192       // 1024
#define SM_WIN 9216       // 8192: win [d][8]
#define SMEM_TOT (17408*4)   // 69632 bytes -> 3 blocks/SM

// Scratch (__device__ globals: allowed; no runtime allocation)
__device__ float g_resA[(size_t)BB*DD*TT];           // checkpoint buffer A (res1, res5)
__device__ float g_resB[(size_t)BB*DD*TT];           // checkpoint buffer B (res3, res7)
__device__ __align__(16) float g_WinT[NCB*DD*8];     // [n][d][c]
__device__ __align__(16) float g_WoutT[NCB*DD*8];    // [n][d][c]
__device__ __align__(16) float g_cbn[NCB*KK*8];      // normalized codebook (ref fp32 semantics)
__device__ __align__(16) float g_cc[NCB*KK];         // sum(c_n*c_n)
__device__ __align__(16) float g_lpart[GB];

// ---------------------------------------------------------------------------
// f32x2 packed helpers (each lane an exact IEEE fp32 op)
// ---------------------------------------------------------------------------
__device__ __forceinline__ unsigned long long pk2(float lo, float hi) {
    unsigned long long r;
    asm("mov.b64 %0, {%1, %2};" : "=l"(r) : "f"(lo), "f"(hi));
    return r;
}
__device__ __forceinline__ void upk2(unsigned long long v, float& lo, float& hi) {
    asm("mov.b64 {%0, %1}, %2;" : "=f"(lo), "=f"(hi) : "l"(v));
}
__device__ __forceinline__ unsigned long long ffma2(unsigned long long a, unsigned long long b, unsigned long long c) {
    unsigned long long r;
    asm("fma.rn.f32x2 %0, %1, %2, %3;" : "=l"(r) : "l"(a), "l"(b), "l"(c));
    return r;
}
__device__ __forceinline__ unsigned long long fmul2(unsigned long long a, unsigned long long b) {
    unsigned long long r;
    asm("mul.rn.f32x2 %0, %1, %2;" : "=l"(r) : "l"(a), "l"(b));
    return r;
}
__device__ __forceinline__ unsigned long long fadd2(unsigned long long a, unsigned long long b) {
    unsigned long long r;
    asm("add.rn.f32x2 %0, %1, %2;" : "=l"(r) : "l"(a), "l"(b));
    return r;
}

// ---------------------------------------------------------------------------
// Prep: weight-norm input rows (fp64 norms), store [n][d][8c]
// ---------------------------------------------------------------------------
__global__ void kp_win(const float* __restrict__ in_v, const float* __restrict__ in_g) {
    const int row = blockIdx.x;               // 0..71 = n*8 + c
    const int n = row >> 3, c = row & 7;
    const float* src = in_v + (size_t)row * DD;
    __shared__ double red[256];
    double ss = 0.0;
    for (int d = threadIdx.x; d < DD; d += 256) { double v = src[d]; ss += v*v; }
    red[threadIdx.x] = ss; __syncthreads();
    for (int s = 128; s > 0; s >>= 1) {
        if (threadIdx.x < s) red[threadIdx.x] += red[threadIdx.x + s];
        __syncthreads();
    }
    const float scale = (float)((double)in_g[row] / sqrt(red[0]));
    for (int d = threadIdx.x; d < DD; d += 256)
        g_WinT[(size_t)n*DD*8 + d*8 + c] = src[d] * scale;
}

// ---------------------------------------------------------------------------
// Prep: weight-norm output rows (norm over C=8, fp64), store [n][d][8c]
// ---------------------------------------------------------------------------
__global__ void kp_wout(const float* __restrict__ out_v, const float* __restrict__ out_g) {
    const int i = blockIdx.x * 256 + threadIdx.x;   // (n, d)
    if (i >= NCB*DD) return;
    const int n = i / DD, d = i - n*DD;
    const float* v = out_v + (size_t)i * 8;
    double ss = 0.0;
    #pragma unroll
    for (int c = 0; c < 8; c++) { double x = v[c]; ss += x*x; }
    const float sc = (float)((double)out_g[i] / sqrt(ss));
    #pragma unroll
    for (int c = 0; c < 8; c++) g_WoutT[(size_t)n*DD*8 + d*8 + c] = v[c] * sc;
}

// ---------------------------------------------------------------------------
// Prep: normalized codebook + cc = sum(c_n^2), replicating fp32 elementwise ops
// ---------------------------------------------------------------------------
__global__ void kp_cb(const float* __restrict__ cb) {
    const int r = blockIdx.x * 256 + threadIdx.x;   // (n, k)
    if (r >= NCB*KK) return;
    const float* v = cb + (size_t)r * 8;
    float ss = 0.f;
    #pragma unroll
    for (int c = 0; c < 8; c++) ss = __fadd_rn(ss, __fmul_rn(v[c], v[c]));
    const float nr = fmaxf(__fsqrt_rn(ss), 1e-12f);
    float cn[8];
    #pragma unroll
    for (int c = 0; c < 8; c++) cn[c] = __fdiv_rn(v[c], nr);
    #pragma unroll
    for (int c = 0; c < 8; c++) g_cbn[(size_t)r*8 + c] = cn[c];
    float s2 = 0.f;
    #pragma unroll
    for (int c = 0; c < 8; c++) s2 = __fadd_rn(s2, __fmul_rn(cn[c], cn[c]));
    g_cc[r] = s2;
}

// ---------------------------------------------------------------------------
// Mega kernel: thread owns one token through all 9 stages + final pass.
// Same arithmetic (values + op order) as the R6 passing kernel; changes are
// storage/scheduling only: wout/ob via __ldg (L1 broadcast), res/z/out streams
// via __ldcs/__stcs, 68KB smem -> 3 blocks/SM for phase overlap.
// ---------------------------------------------------------------------------
__global__ void __launch_bounds__(THREADS, 3) k_mega(const float* __restrict__ z,
                                                     const float* __restrict__ in_b,
                                                     const float* __restrict__ out_b,
                                                     const float* __restrict__ cb_raw,
                                                     float* __restrict__ out) {
    extern __shared__ float smf[];
    __shared__ float red[THREADS];

    const int tid = threadIdx.x;
    const int token = blockIdx.x * THREADS + tid;
    const int b = token >> 13;
    const int t = token & (TT - 1);
    const size_t off = (size_t)b*DD*TT + t;

    float zqA[8] = {0,0,0,0,0,0,0,0};   // zqst of stage n-1
    float zqB[8] = {0,0,0,0,0,0,0,0};   // zqst of stage n-2
    float lacc = 0.f;

    for (int n = 0; n < NCB; n++) {
        const int nproj = (n == 0) ? 0 : (((n & 1) && n >= 3) ? 2 : 1);
        const int m0 = n - nproj;
        const float* rin = (n <= 1) ? z
                          : ((n == 2 || n == 3 || n == 6 || n == 7) ? (const float*)g_resA
                                                                    : (const float*)g_resB);
        float* wr = nullptr;
        if (n == 1) wr = g_resA;
        else if (n == 3) wr = g_resB;
        else if (n == 5) wr = g_resA;
        else if (n == 7) wr = g_resB;

        __syncthreads();   // previous stage done with smem
        for (int i = tid; i < KK*8; i += THREADS) {
            const int k = i >> 3, c = i & 7;
            smf[SM_CB2 + (k >> 1)*16 + c*2 + (k & 1)] = g_cbn[(size_t)n*KK*8 + i];
        }
        for (int k = tid; k < KK; k += THREADS) smf[SM_CC2 + k] = g_cc[n*KK + k];
        for (int i = tid; i < DD*8; i += THREADS) smf[SM_WIN + i] = g_WinT[(size_t)n*DD*8 + i];
        __syncthreads();

        const float* wo0 = g_WoutT + (size_t)m0*DD*8;
        const float* wo1 = g_WoutT + (size_t)(m0 + 1)*DD*8;
        const float* ob0 = out_b + (size_t)m0*DD;
        const float* ob1 = out_b + (size_t)(m0 + 1)*DD;

        // first-projection operand: zqst_{m0} = (nproj==2 ? zqB : zqA)
        float zp[8];
        #pragma unroll
        for (int c = 0; c < 8; c++) zp[c] = (nproj == 2) ? zqB[c] : zqA[c];

        // ---- Phase 1: stream residual, apply projections, accumulate z_e ----
        unsigned long long accp[4] = {0ull, 0ull, 0ull, 0ull};
        float rbuf[8];
        #pragma unroll
        for (int i = 0; i < 8; i++) rbuf[i] = __ldcs(rin + off + (size_t)i*TT);

        for (int d0 = 0; d0 < DD; d0 += 8) {
            float rnx[8];
            const bool more = (d0 + 8) < DD;
            if (more) {
                #pragma unroll
                for (int i = 0; i < 8; i++)
                    rnx[i] = __ldcs(rin + off + (size_t)(d0 + 8 + i)*TT);
            }
            #pragma unroll
            for (int i = 0; i < 8; i++) {
                const int d = d0 + i;
                float r = rbuf[i];
                if (nproj >= 1) {
                    const float4 wa = __ldg((const float4*)(wo0 + d*8));
                    const float4 wb = __ldg((const float4*)(wo0 + d*8 + 4));
                    float dt = 0.f;
                    dt = fmaf(wa.x, zp[0], dt);
                    dt = fmaf(wa.y, zp[1], dt);
                    dt = fmaf(wa.z, zp[2], dt);
                    dt = fmaf(wa.w, zp[3], dt);
                    dt = fmaf(wb.x, zp[4], dt);
                    dt = fmaf(wb.y, zp[5], dt);
                    dt = fmaf(wb.z, zp[6], dt);
                    dt = fmaf(wb.w, zp[7], dt);
                    const float pr = __fadd_rn(dt, __ldg(ob0 + d));
                    r = __fsub_rn(r, pr);
                }
                if (nproj == 2) {
                    const float4 wa = __ldg((const float4*)(wo1 + d*8));
                    const float4 wb = __ldg((const float4*)(wo1 + d*8 + 4));
                    float dt = 0.f;
                    dt = fmaf(wa.x, zqA[0], dt);
                    dt = fmaf(wa.y, zqA[1], dt);
                    dt = fmaf(wa.z, zqA[2], dt);
                    dt = fmaf(wa.w, zqA[3], dt);
                    dt = fmaf(wb.x, zqA[4], dt);
                    dt = fmaf(wb.y, zqA[5], dt);
                    dt = fmaf(wb.z, zqA[6], dt);
                    dt = fmaf(wb.w, zqA[7], dt);
                    const float pr = __fadd_rn(dt, __ldg(ob1 + d));
                    r = __fsub_rn(r, pr);
                }
                if (wr) __stcs(wr + off + (size_t)d*TT, r);
                // z_e accumulation: win pairs read directly as packed f32x2
                const ulonglong2 w01 = *(const ulonglong2*)&smf[SM_WIN + d*8];
                const ulonglong2 w23 = *(const ulonglong2*)&smf[SM_WIN + d*8 + 4];
                const unsigned long long rp = pk2(r, r);
                accp[0] = ffma2(w01.x, rp, accp[0]);
                accp[1] = ffma2(w01.y, rp, accp[1]);
                accp[2] = ffma2(w23.x, rp, accp[2]);
                accp[3] = ffma2(w23.y, rp, accp[3]);
            }
            if (more) {
                #pragma unroll
                for (int i = 0; i < 8; i++) rbuf[i] = rnx[i];
            }
        }

        // ---- Phase 2: z_e, normalize (identical ops) ----
        float e[8];
        upk2(accp[0], e[0], e[1]); upk2(accp[1], e[2], e[3]);
        upk2(accp[2], e[4], e[5]); upk2(accp[3], e[6], e[7]);
        #pragma unroll
        for (int c = 0; c < 8; c++) e[c] = __fadd_rn(e[c], __ldg(in_b + n*8 + c));

        float ssq = 0.f;
        #pragma unroll
        for (int c = 0; c < 8; c++) ssq = __fadd_rn(ssq, __fmul_rn(e[c], e[c]));
        const float rho = fmaxf(__fsqrt_rn(ssq), 1e-12f);
        float en[8];
        #pragma unroll
        for (int c = 0; c < 8; c++) en[c] = __fdiv_rn(e[c], rho);
        float ee = 0.f;
        #pragma unroll
        for (int c = 0; c < 8; c++) ee = __fadd_rn(ee, __fmul_rn(en[c], en[c]));

        unsigned long long en2[8];
        #pragma unroll
        for (int c = 0; c < 8; c++) en2[c] = pk2(en[c], en[c]);
        const unsigned long long eep = pk2(ee, ee);
        const unsigned long long m2  = pk2(-2.f, -2.f);

        // ---- argmin: per-k dist bit-identical; 4 chains, exact first-wins merge ----
        float bA = 3.4e38f, bBv = 3.4e38f, bC = 3.4e38f, bD = 3.4e38f;
        int   iA = 0, iB = 0, iC = 0, iD = 0;
        const unsigned long long* cbu = (const unsigned long long*)&smf[SM_CB2];
        const unsigned long long* ccu = (const unsigned long long*)&smf[SM_CC2];
        #pragma unroll 2
        for (int k2 = 0; k2 < KK/2; k2 += 2) {
            const ulonglong2 ca0 = *(const ulonglong2*)(cbu + k2*8);
            const ulonglong2 cb0 = *(const ulonglong2*)(cbu + k2*8 + 2);
            const ulonglong2 cc0 = *(const ulonglong2*)(cbu + k2*8 + 4);
            const ulonglong2 cd0 = *(const ulonglong2*)(cbu + k2*8 + 6);
            const ulonglong2 ca1 = *(const ulonglong2*)(cbu + (k2+1)*8);
            const ulonglong2 cb1 = *(const ulonglong2*)(cbu + (k2+1)*8 + 2);
            const ulonglong2 cc1 = *(const ulonglong2*)(cbu + (k2+1)*8 + 4);
            const ulonglong2 cd1 = *(const ulonglong2*)(cbu + (k2+1)*8 + 6);
            unsigned long long dp0 = fmul2(en2[0], ca0.x);
            unsigned long long dp1 = fmul2(en2[0], ca1.x);
            dp0 = ffma2(en2[1], ca0.y, dp0);  dp1 = ffma2(en2[1], ca1.y, dp1);
            dp0 = ffma2(en2[2], cb0.x, dp0);  dp1 = ffma2(en2[2], cb1.x, dp1);
            dp0 = ffma2(en2[3], cb0.y, dp0);  dp1 = ffma2(en2[3], cb1.y, dp1);
            dp0 = ffma2(en2[4], cc0.x, dp0);  dp1 = ffma2(en2[4], cc1.x, dp1);
            dp0 = ffma2(en2[5], cc0.y, dp0);  dp1 = ffma2(en2[5], cc1.y, dp1);
            dp0 = ffma2(en2[6], cd0.x, dp0);  dp1 = ffma2(en2[6], cd1.x, dp1);
            dp0 = ffma2(en2[7], cd0.y, dp0);  dp1 = ffma2(en2[7], cd1.y, dp1);
            const unsigned long long t0 = ffma2(m2, dp0, eep);
            const unsigned long long t1 = ffma2(m2, dp1, eep);
            const unsigned long long di0 = fadd2(t0, ccu[k2]);
            const unsigned long long di1 = fadd2(t1, ccu[k2+1]);
            float d0v, d1v, d2v, d3v;
            upk2(di0, d0v, d1v); upk2(di1, d2v, d3v);
            if (d0v < bA)  { bA = d0v;  iA = 2*k2; }
            if (d1v < bBv) { bBv = d1v; iB = 2*k2 + 1; }
            if (d2v < bC)  { bC = d2v;  iC = 2*k2 + 2; }
            if (d3v < bD)  { bD = d3v;  iD = 2*k2 + 3; }
        }
        float best = bA; int bi = iA;
        if (bBv < best || (bBv == best && iB < bi)) { best = bBv; bi = iB; }
        if (bC  < best || (bC  == best && iC < bi)) { best = bC;  bi = iC; }
        if (bD  < best || (bD  == best && iD < bi)) { best = bD;  bi = iD; }

        // ---- Phase 3: winner, straight-through, outputs ----
        const float* qsrc = cb_raw + ((size_t)n*KK + bi)*8;
        const float4 q0 = __ldg((const float4*)qsrc);
        const float4 q1 = __ldg((const float4*)(qsrc + 4));
        const float q[8] = {q0.x, q0.y, q0.z, q0.w, q1.x, q1.y, q1.z, q1.w};

        float zst[8];
        #pragma unroll
        for (int c = 0; c < 8; c++) {
            const float dl = __fsub_rn(e[c], q[c]);
            lacc = fmaf(dl, dl, lacc);
            zst[c] = __fadd_rn(e[c], __fsub_rn(q[c], e[c]));   // z_e + (z_q - z_e)
        }

        __stcs(&out[OFF_CODES + (size_t)b*NCB*TT + (size_t)n*TT + t], (float)bi);
        #pragma unroll
        for (int c = 0; c < 8; c++)
            __stcs(&out[OFF_LAT + (size_t)b*CN*TT + (size_t)(n*8 + c)*TT + t], e[c]);

        #pragma unroll
        for (int c = 0; c < 8; c++) { zqB[c] = zqA[c]; zqA[c] = zst[c]; }
    }

    // ---- Final pass: res7(B) -> fly res8 (proj7, zqB) -> res9 (proj8, zqA) ----
    {
        const float* wo7 = g_WoutT + (size_t)7*DD*8;
        const float* wo8 = g_WoutT + (size_t)8*DD*8;
        const float* ob7 = out_b + (size_t)7*DD;
        const float* ob8 = out_b + (size_t)8*DD;

        float rb[8], zb[8];
        #pragma unroll
        for (int i = 0; i < 8; i++) {
            rb[i] = __ldcs((const float*)g_resB + off + (size_t)i*TT);
            zb[i] = __ldcs(z + off + (size_t)i*TT);
        }
        for (int d0 = 0; d0 < DD; d0 += 8) {
            float rn_[8], zn_[8];
            const bool more = (d0 + 8) < DD;
            if (more) {
                #pragma unroll
                for (int i = 0; i < 8; i++) {
                    rn_[i] = __ldcs((const float*)g_resB + off + (size_t)(d0 + 8 + i)*TT);
                    zn_[i] = __ldcs(z + off + (size_t)(d0 + 8 + i)*TT);
                }
            }
            #pragma unroll
            for (int i = 0; i < 8; i++) {
                const int d = d0 + i;
                float r = rb[i];
                {   // proj7 (exactly what stage 8 computed on the fly)
                    const float4 wa = __ldg((const float4*)(wo7 + d*8));
                    const float4 wb = __ldg((const float4*)(wo7 + d*8 + 4));
                    float dt = 0.f;
                    dt = fmaf(wa.x, zqB[0], dt);
                    dt = fmaf(wa.y, zqB[1], dt);
                    dt = fmaf(wa.z, zqB[2], dt);
                    dt = fmaf(wa.w, zqB[3], dt);
                    dt = fmaf(wb.x, zqB[4], dt);
                    dt = fmaf(wb.y, zqB[5], dt);
                    dt = fmaf(wb.z, zqB[6], dt);
                    dt = fmaf(wb.w, zqB[7], dt);
                    const float pr = __fadd_rn(dt, __ldg(ob7 + d));
                    r = __fsub_rn(r, pr);
                }
                {   // proj8
                    const float4 wa = __ldg((const float4*)(wo8 + d*8));
                    const float4 wb = __ldg((const float4*)(wo8 + d*8 + 4));
                    float dt = 0.f;
                    dt = fmaf(wa.x, zqA[0], dt);
                    dt = fmaf(wa.y, zqA[1], dt);
                    dt = fmaf(wa.z, zqA[2], dt);
                    dt = fmaf(wa.w, zqA[3], dt);
                    dt = fmaf(wb.x, zqA[4], dt);
                    dt = fmaf(wb.y, zqA[5], dt);
                    dt = fmaf(wb.z, zqA[6], dt);
                    dt = fmaf(wb.w, zqA[7], dt);
                    const float pr = __fadd_rn(dt, __ldg(ob8 + d));
                    r = __fsub_rn(r, pr);
                }
                __stcs(&out[off + (size_t)d*TT], __fsub_rn(zb[i], r));
            }
            if (more) {
                #pragma unroll
                for (int i = 0; i < 8; i++) { rb[i] = rn_[i]; zb[i] = zn_[i]; }
            }
        }
    }

    // ---- loss partial ----
    red[tid] = lacc; __syncthreads();
    for (int s = THREADS/2; s > 0; s >>= 1) {
        if (tid < s) red[tid] += red[tid + s];
        __syncthreads();
    }
    if (tid == 0) g_lpart[blockIdx.x] = red[0];
}

// ---------------------------------------------------------------------------
// Deterministic loss reduce in fp64: cl == cbl (identical forward values)
// ---------------------------------------------------------------------------
__global__ void k_loss(float* __restrict__ out) {
    if (threadIdx.x != 0 || blockIdx.x != 0) return;
    double s = 0.0;
    for (int i = 0; i < GB; i++) s += (double)g_lpart[i];
    const float v = (float)(s / 524288.0);   // per-stage mean over B*C*T, summed
    out[OFF_CL]     = v;
    out[OFF_CL + 1] = v;
}

// ---------------------------------------------------------------------------
extern "C" void kernel_launch(void* const* d_in, const int* in_sizes, int n_in,
                              void* d_out, int out_size) {
    (void)in_sizes; (void)n_in; (void)out_size;
    const float* z     = (const float*)d_in[0];
    const float* in_v  = (const float*)d_in[1];
    const float* in_g  = (const float*)d_in[2];
    const float* in_b  = (const float*)d_in[3];
    const float* out_v = (const float*)d_in[4];
    const float* out_g = (const float*)d_in[5];
    const float* out_b = (const float*)d_in[6];
    const float* cb    = (const float*)d_in[7];
    float* out = (float*)d_out;

    cudaFuncSetAttribute(k_mega, cudaFuncAttributeMaxDynamicSharedMemorySize, SMEM_TOT);

    kp_win  <<<72, 256>>>(in_v, in_g);
    kp_wout <<<(NCB*DD + 255)/256, 256>>>(out_v, out_g);
    kp_cb   <<<(NCB*KK + 255)/256, 256>>>(cb);

    k_mega <<<GB, THREADS, SMEM_TOT>>>(z, in_b, out_b, cb, out);
    k_loss <<<1, 32>>>(out);
}

// round 8
// speedup vs baseline: 3.2657x; 3.2657x over previous
#include <cuda_runtime.h>
#include <cstdint>

// Problem dims
#define BB 8
#define DD 1024
#define TT 8192
#define NCB 9
#define KK 1024
#define NT (BB*TT)        // 65536 tokens
#define CN (NCB*8)        // 72

// Output layout (float32, tuple flattened in order)
#define OFF_CODES ((size_t)BB*DD*TT)                  // 67108864
#define OFF_LAT   (OFF_CODES + (size_t)BB*NCB*TT)     // 67698688
#define OFF_CL    (OFF_LAT + (size_t)BB*CN*TT)        // 72417280

#define THREADS 448
#define NBLK 152

// Dynamic smem layout (float indices) — identical to R6
#define SM_CB2 0          // 8192: codebook pair-interleaved
#define SM_CC2 8192       // 1024
#define SM_WIN 9216       // 8192: win [d][8]
#define SM_WO0 17408      // 8192: wout table 0
#define SM_WO1 25600      // 8192: wout table 1
#define SM_OB0 33792      // 1024
#define SM_OB1 34816      // 1024
#define SMEM_TOT (35840*4)   // 143360 bytes -> 1 block/SM

// Scratch (__device__ globals: allowed; no runtime allocation)
__device__ float g_resA[(size_t)BB*DD*TT];           // checkpoint buffer A (res1, res5)
__device__ float g_resB[(size_t)BB*DD*TT];           // checkpoint buffer B (res3, res7)
__device__ __align__(16) float g_WinT[NCB*DD*8];     // [n][d][c]
__device__ __align__(16) float g_WoutT[NCB*DD*8];    // [n][d][c]
__device__ __align__(16) float g_cbn[NCB*KK*8];      // normalized codebook (ref fp32 semantics)
__device__ __align__(16) float g_cc[NCB*KK];         // sum(c_n*c_n)
__device__ __align__(16) float g_lpart[NBLK];

// ---------------------------------------------------------------------------
// f32x2 packed helpers (each lane an exact IEEE fp32 op)
// ---------------------------------------------------------------------------
__device__ __forceinline__ unsigned long long pk2(float lo, float hi) {
    unsigned long long r;
    asm("mov.b64 %0, {%1, %2};" : "=l"(r) : "f"(lo), "f"(hi));
    return r;
}
__device__ __forceinline__ void upk2(unsigned long long v, float& lo, float& hi) {
    asm("mov.b64 {%0, %1}, %2;" : "=f"(lo), "=f"(hi) : "l"(v));
}
__device__ __forceinline__ unsigned long long ffma2(unsigned long long a, unsigned long long b, unsigned long long c) {
    unsigned long long r;
    asm("fma.rn.f32x2 %0, %1, %2, %3;" : "=l"(r) : "l"(a), "l"(b), "l"(c));
    return r;
}
__device__ __forceinline__ unsigned long long fmul2(unsigned long long a, unsigned long long b) {
    unsigned long long r;
    asm("mul.rn.f32x2 %0, %1, %2;" : "=l"(r) : "l"(a), "l"(b));
    return r;
}
__device__ __forceinline__ unsigned long long fadd2(unsigned long long a, unsigned long long b) {
    unsigned long long r;
    asm("add.rn.f32x2 %0, %1, %2;" : "=l"(r) : "l"(a), "l"(b));
    return r;
}

// ---------------------------------------------------------------------------
// Prep: weight-norm input rows (fp64 norms), store [n][d][8c]
// ---------------------------------------------------------------------------
__global__ void kp_win(const float* __restrict__ in_v, const float* __restrict__ in_g) {
    const int row = blockIdx.x;               // 0..71 = n*8 + c
    const int n = row >> 3, c = row & 7;
    const float* src = in_v + (size_t)row * DD;
    __shared__ double red[256];
    double ss = 0.0;
    for (int d = threadIdx.x; d < DD; d += 256) { double v = src[d]; ss += v*v; }
    red[threadIdx.x] = ss; __syncthreads();
    for (int s = 128; s > 0; s >>= 1) {
        if (threadIdx.x < s) red[threadIdx.x] += red[threadIdx.x + s];
        __syncthreads();
    }
    const float scale = (float)((double)in_g[row] / sqrt(red[0]));
    for (int d = threadIdx.x; d < DD; d += 256)
        g_WinT[(size_t)n*DD*8 + d*8 + c] = src[d] * scale;
}

// ---------------------------------------------------------------------------
// Prep: weight-norm output rows (norm over C=8, fp64), store [n][d][8c]
// ---------------------------------------------------------------------------
__global__ void kp_wout(const float* __restrict__ out_v, const float* __restrict__ out_g) {
    const int i = blockIdx.x * 256 + threadIdx.x;   // (n, d)
    if (i >= NCB*DD) return;
    const int n = i / DD, d = i - n*DD;
    const float* v = out_v + (size_t)i * 8;
    double ss = 0.0;
    #pragma unroll
    for (int c = 0; c < 8; c++) { double x = v[c]; ss += x*x; }
    const float sc = (float)((double)out_g[i] / sqrt(ss));
    #pragma unroll
    for (int c = 0; c < 8; c++) g_WoutT[(size_t)n*DD*8 + d*8 + c] = v[c] * sc;
}

// ---------------------------------------------------------------------------
// Prep: normalized codebook + cc = sum(c_n^2), replicating fp32 elementwise ops
// ---------------------------------------------------------------------------
__global__ void kp_cb(const float* __restrict__ cb) {
    const int r = blockIdx.x * 256 + threadIdx.x;   // (n, k)
    if (r >= NCB*KK) return;
    const float* v = cb + (size_t)r * 8;
    float ss = 0.f;
    #pragma unroll
    for (int c = 0; c < 8; c++) ss = __fadd_rn(ss, __fmul_rn(v[c], v[c]));
    const float nr = fmaxf(__fsqrt_rn(ss), 1e-12f);
    float cn[8];
    #pragma unroll
    for (int c = 0; c < 8; c++) cn[c] = __fdiv_rn(v[c], nr);
    #pragma unroll
    for (int c = 0; c < 8; c++) g_cbn[(size_t)r*8 + c] = cn[c];
    float s2 = 0.f;
    #pragma unroll
    for (int c = 0; c < 8; c++) s2 = __fadd_rn(s2, __fmul_rn(cn[c], cn[c]));
    g_cc[r] = s2;
}

// ---------------------------------------------------------------------------
// Mega kernel: thread owns one token through all 9 stages + final pass.
// Arithmetic identical to the R6 passing kernel (same values, same op order).
// Deltas vs R6 (scheduling only): 152 blocks x 448 threads (full SM coverage;
// surplus threads clamp to the last token and duplicate its identical work),
// 16-deep streaming prefetch in the stage loop.
// ---------------------------------------------------------------------------
__global__ void __launch_bounds__(THREADS) k_mega(const float* __restrict__ z,
                                                  const float* __restrict__ in_b,
                                                  const float* __restrict__ out_b,
                                                  const float* __restrict__ cb_raw,
                                                  float* __restrict__ out) {
    extern __shared__ float smf[];
    __shared__ float red[512];

    const int tid = threadIdx.x;
    int token = blockIdx.x * THREADS + tid;
    const int active = (token < NT) ? 1 : 0;
    if (!active) token = NT - 1;   // duplicate last token's work (identical writes)
    const int b = token >> 13;
    const int t = token & (TT - 1);
    const size_t off = (size_t)b*DD*TT + t;

    float zqA[8] = {0,0,0,0,0,0,0,0};   // zqst of stage n-1
    float zqB[8] = {0,0,0,0,0,0,0,0};   // zqst of stage n-2
    float lacc = 0.f;

    for (int n = 0; n < NCB; n++) {
        const int nproj = (n == 0) ? 0 : (((n & 1) && n >= 3) ? 2 : 1);
        const int m0 = n - nproj;
        const float* rin = (n <= 1) ? z
                          : ((n == 2 || n == 3 || n == 6 || n == 7) ? (const float*)g_resA
                                                                    : (const float*)g_resB);
        float* wr = nullptr;
        if (n == 1) wr = g_resA;
        else if (n == 3) wr = g_resB;
        else if (n == 5) wr = g_resA;
        else if (n == 7) wr = g_resB;

        __syncthreads();   // previous stage done with smem
        for (int i = tid; i < KK*8; i += THREADS) {
            const int k = i >> 3, c = i & 7;
            smf[SM_CB2 + (k >> 1)*16 + c*2 + (k & 1)] = g_cbn[(size_t)n*KK*8 + i];
        }
        for (int k = tid; k < KK; k += THREADS) smf[SM_CC2 + k] = g_cc[n*KK + k];
        for (int i = tid; i < DD*8; i += THREADS) smf[SM_WIN + i] = g_WinT[(size_t)n*DD*8 + i];
        if (nproj >= 1) {
            for (int i = tid; i < DD*8; i += THREADS)
                smf[SM_WO0 + i] = g_WoutT[(size_t)m0*DD*8 + i];
            for (int i = tid; i < DD; i += THREADS)
                smf[SM_OB0 + i] = out_b[m0*DD + i];
        }
        if (nproj == 2) {
            for (int i = tid; i < DD*8; i += THREADS)
                smf[SM_WO1 + i] = g_WoutT[(size_t)(m0 + 1)*DD*8 + i];
            for (int i = tid; i < DD; i += THREADS)
                smf[SM_OB1 + i] = out_b[(m0 + 1)*DD + i];
        }
        __syncthreads();

        // first-projection operand: zqst_{m0} = (nproj==2 ? zqB : zqA)
        float zp[8];
        #pragma unroll
        for (int c = 0; c < 8; c++) zp[c] = (nproj == 2) ? zqB[c] : zqA[c];

        // ---- Phase 1: stream residual, apply projections, accumulate z_e ----
        unsigned long long accp[4] = {0ull, 0ull, 0ull, 0ull};
        float rbuf[16];
        #pragma unroll
        for (int i = 0; i < 16; i++) rbuf[i] = rin[off + (size_t)i*TT];

        for (int d0 = 0; d0 < DD; d0 += 16) {
            float rnx[16];
            const bool more = (d0 + 16) < DD;
            if (more) {
                #pragma unroll
                for (int i = 0; i < 16; i++)
                    rnx[i] = rin[off + (size_t)(d0 + 16 + i)*TT];
            }
            #pragma unroll
            for (int i = 0; i < 16; i++) {
                const int d = d0 + i;
                float r = rbuf[i];
                if (nproj >= 1) {
                    const float4 wa = *(const float4*)&smf[SM_WO0 + d*8];
                    const float4 wb = *(const float4*)&smf[SM_WO0 + d*8 + 4];
                    float dt = 0.f;
                    dt = fmaf(wa.x, zp[0], dt);
                    dt = fmaf(wa.y, zp[1], dt);
                    dt = fmaf(wa.z, zp[2], dt);
                    dt = fmaf(wa.w, zp[3], dt);
                    dt = fmaf(wb.x, zp[4], dt);
                    dt = fmaf(wb.y, zp[5], dt);
                    dt = fmaf(wb.z, zp[6], dt);
                    dt = fmaf(wb.w, zp[7], dt);
                    const float pr = __fadd_rn(dt, smf[SM_OB0 + d]);
                    r = __fsub_rn(r, pr);
                }
                if (nproj == 2) {
                    const float4 wa = *(const float4*)&smf[SM_WO1 + d*8];
                    const float4 wb = *(const float4*)&smf[SM_WO1 + d*8 + 4];
                    float dt = 0.f;
                    dt = fmaf(wa.x, zqA[0], dt);
                    dt = fmaf(wa.y, zqA[1], dt);
                    dt = fmaf(wa.z, zqA[2], dt);
                    dt = fmaf(wa.w, zqA[3], dt);
                    dt = fmaf(wb.x, zqA[4], dt);
                    dt = fmaf(wb.y, zqA[5], dt);
                    dt = fmaf(wb.z, zqA[6], dt);
                    dt = fmaf(wb.w, zqA[7], dt);
                    const float pr = __fadd_rn(dt, smf[SM_OB1 + d]);
                    r = __fsub_rn(r, pr);
                }
                if (wr) wr[off + (size_t)d*TT] = r;
                // z_e accumulation: win pairs read directly as packed f32x2
                const ulonglong2 w01 = *(const ulonglong2*)&smf[SM_WIN + d*8];
                const ulonglong2 w23 = *(const ulonglong2*)&smf[SM_WIN + d*8 + 4];
                const unsigned long long rp = pk2(r, r);
                accp[0] = ffma2(w01.x, rp, accp[0]);
                accp[1] = ffma2(w01.y, rp, accp[1]);
                accp[2] = ffma2(w23.x, rp, accp[2]);
                accp[3] = ffma2(w23.y, rp, accp[3]);
            }
            if (more) {
                #pragma unroll
                for (int i = 0; i < 16; i++) rbuf[i] = rnx[i];
            }
        }

        // ---- Phase 2: z_e, normalize (identical ops) ----
        float e[8];
        upk2(accp[0], e[0], e[1]); upk2(accp[1], e[2], e[3]);
        upk2(accp[2], e[4], e[5]); upk2(accp[3], e[6], e[7]);
        #pragma unroll
        for (int c = 0; c < 8; c++) e[c] = __fadd_rn(e[c], __ldg(in_b + n*8 + c));

        float ssq = 0.f;
        #pragma unroll
        for (int c = 0; c < 8; c++) ssq = __fadd_rn(ssq, __fmul_rn(e[c], e[c]));
        const float rho = fmaxf(__fsqrt_rn(ssq), 1e-12f);
        float en[8];
        #pragma unroll
        for (int c = 0; c < 8; c++) en[c] = __fdiv_rn(e[c], rho);
        float ee = 0.f;
        #pragma unroll
        for (int c = 0; c < 8; c++) ee = __fadd_rn(ee, __fmul_rn(en[c], en[c]));

        unsigned long long en2[8];
        #pragma unroll
        for (int c = 0; c < 8; c++) en2[c] = pk2(en[c], en[c]);
        const unsigned long long eep = pk2(ee, ee);
        const unsigned long long m2  = pk2(-2.f, -2.f);

        // ---- argmin: per-k dist bit-identical; 4 chains, exact first-wins merge ----
        float bA = 3.4e38f, bBv = 3.4e38f, bC = 3.4e38f, bD = 3.4e38f;
        int   iA = 0, iB = 0, iC = 0, iD = 0;
        const unsigned long long* cbu = (const unsigned long long*)&smf[SM_CB2];
        const unsigned long long* ccu = (const unsigned long long*)&smf[SM_CC2];
        #pragma unroll 2
        for (int k2 = 0; k2 < KK/2; k2 += 2) {
            const ulonglong2 ca0 = *(const ulonglong2*)(cbu + k2*8);
            const ulonglong2 cb0 = *(const ulonglong2*)(cbu + k2*8 + 2);
            const ulonglong2 cc0 = *(const ulonglong2*)(cbu + k2*8 + 4);
            const ulonglong2 cd0 = *(const ulonglong2*)(cbu + k2*8 + 6);
            const ulonglong2 ca1 = *(const ulonglong2*)(cbu + (k2+1)*8);
            const ulonglong2 cb1 = *(const ulonglong2*)(cbu + (k2+1)*8 + 2);
            const ulonglong2 cc1 = *(const ulonglong2*)(cbu + (k2+1)*8 + 4);
            const ulonglong2 cd1 = *(const ulonglong2*)(cbu + (k2+1)*8 + 6);
            unsigned long long dp0 = fmul2(en2[0], ca0.x);
            unsigned long long dp1 = fmul2(en2[0], ca1.x);
            dp0 = ffma2(en2[1], ca0.y, dp0);  dp1 = ffma2(en2[1], ca1.y, dp1);
            dp0 = ffma2(en2[2], cb0.x, dp0);  dp1 = ffma2(en2[2], cb1.x, dp1);
            dp0 = ffma2(en2[3], cb0.y, dp0);  dp1 = ffma2(en2[3], cb1.y, dp1);
            dp0 = ffma2(en2[4], cc0.x, dp0);  dp1 = ffma2(en2[4], cc1.x, dp1);
            dp0 = ffma2(en2[5], cc0.y, dp0);  dp1 = ffma2(en2[5], cc1.y, dp1);
            dp0 = ffma2(en2[6], cd0.x, dp0);  dp1 = ffma2(en2[6], cd1.x, dp1);
            dp0 = ffma2(en2[7], cd0.y, dp0);  dp1 = ffma2(en2[7], cd1.y, dp1);
            const unsigned long long t0 = ffma2(m2, dp0, eep);
            const unsigned long long t1 = ffma2(m2, dp1, eep);
            const unsigned long long di0 = fadd2(t0, ccu[k2]);
            const unsigned long long di1 = fadd2(t1, ccu[k2+1]);
            float d0v, d1v, d2v, d3v;
            upk2(di0, d0v, d1v); upk2(di1, d2v, d3v);
            if (d0v < bA)  { bA = d0v;  iA = 2*k2; }
            if (d1v < bBv) { bBv = d1v; iB = 2*k2 + 1; }
            if (d2v < bC)  { bC = d2v;  iC = 2*k2 + 2; }
            if (d3v < bD)  { bD = d3v;  iD = 2*k2 + 3; }
        }
        float best = bA; int bi = iA;
        if (bBv < best || (bBv == best && iB < bi)) { best = bBv; bi = iB; }
        if (bC  < best || (bC  == best && iC < bi)) { best = bC;  bi = iC; }
        if (bD  < best || (bD  == best && iD < bi)) { best = bD;  bi = iD; }

        // ---- Phase 3: winner, straight-through, outputs ----
        const float* qsrc = cb_raw + ((size_t)n*KK + bi)*8;
        const float4 q0 = __ldg((const float4*)qsrc);
        const float4 q1 = __ldg((const float4*)(qsrc + 4));
        const float q[8] = {q0.x, q0.y, q0.z, q0.w, q1.x, q1.y, q1.z, q1.w};

        float zst[8];
        #pragma unroll
        for (int c = 0; c < 8; c++) {
            const float dl = __fsub_rn(e[c], q[c]);
            lacc = fmaf(dl, dl, lacc);
            zst[c] = __fadd_rn(e[c], __fsub_rn(q[c], e[c]));   // z_e + (z_q - z_e)
        }

        out[OFF_CODES + (size_t)b*NCB*TT + (size_t)n*TT + t] = (float)bi;
        #pragma unroll
        for (int c = 0; c < 8; c++)
            out[OFF_LAT + (size_t)b*CN*TT + (size_t)(n*8 + c)*TT + t] = e[c];

        #pragma unroll
        for (int c = 0; c < 8; c++) { zqB[c] = zqA[c]; zqA[c] = zst[c]; }
    }

    // ---- Final pass: res7(B) -> fly res8 (proj7, zqB) -> res9 (proj8, zqA) ----
    __syncthreads();
    for (int i = tid; i < DD*8; i += THREADS) {
        smf[SM_WO0 + i] = g_WoutT[(size_t)7*DD*8 + i];
        smf[SM_WO1 + i] = g_WoutT[(size_t)8*DD*8 + i];
    }
    for (int i = tid; i < DD; i += THREADS) {
        smf[SM_OB0 + i] = out_b[7*DD + i];
        smf[SM_OB1 + i] = out_b[8*DD + i];
    }
    __syncthreads();

    {
        float rb[8], zb[8];
        #pragma unroll
        for (int i = 0; i < 8; i++) {
            rb[i] = g_resB[off + (size_t)i*TT];
            zb[i] = __ldg(z + off + (size_t)i*TT);
        }
        for (int d0 = 0; d0 < DD; d0 += 8) {
            float rn_[8], zn_[8];
            const bool more = (d0 + 8) < DD;
            if (more) {
                #pragma unroll
                for (int i = 0; i < 8; i++) {
                    rn_[i] = g_resB[off + (size_t)(d0 + 8 + i)*TT];
                    zn_[i] = __ldg(z + off + (size_t)(d0 + 8 + i)*TT);
                }
            }
            #pragma unroll
            for (int i = 0; i < 8; i++) {
                const int d = d0 + i;
                float r = rb[i];
                {   // proj7 (exactly what stage 8 computed on the fly)
                    const float4 wa = *(const float4*)&smf[SM_WO0 + d*8];
                    const float4 wb = *(const float4*)&smf[SM_WO0 + d*8 + 4];
                    float dt = 0.f;
                    dt = fmaf(wa.x, zqB[0], dt);
                    dt = fmaf(wa.y, zqB[1], dt);
                    dt = fmaf(wa.z, zqB[2], dt);
                    dt = fmaf(wa.w, zqB[3], dt);
                    dt = fmaf(wb.x, zqB[4], dt);
                    dt = fmaf(wb.y, zqB[5], dt);
                    dt = fmaf(wb.z, zqB[6], dt);
                    dt = fmaf(wb.w, zqB[7], dt);
                    const float pr = __fadd_rn(dt, smf[SM_OB0 + d]);
                    r = __fsub_rn(r, pr);
                }
                {   // proj8
                    const float4 wa = *(const float4*)&smf[SM_WO1 + d*8];
                    const float4 wb = *(const float4*)&smf[SM_WO1 + d*8 + 4];
                    float dt = 0.f;
                    dt = fmaf(wa.x, zqA[0], dt);
                    dt = fmaf(wa.y, zqA[1], dt);
                    dt = fmaf(wa.z, zqA[2], dt);
                    dt = fmaf(wa.w, zqA[3], dt);
                    dt = fmaf(wb.x, zqA[4], dt);
                    dt = fmaf(wb.y, zqA[5], dt);
                    dt = fmaf(wb.z, zqA[6], dt);
                    dt = fmaf(wb.w, zqA[7], dt);
                    const float pr = __fadd_rn(dt, smf[SM_OB1 + d]);
                    r = __fsub_rn(r, pr);
                }
                out[off + (size_t)d*TT] = __fsub_rn(zb[i], r);
            }
            if (more) {
                #pragma unroll
                for (int i = 0; i < 8; i++) { rb[i] = rn_[i]; zb[i] = zn_[i]; }
            }
        }
    }

    // ---- loss partial (inactive clones contribute 0) ----
    red[tid] = active ? lacc : 0.f;
    if (tid < 512 - THREADS) red[THREADS + tid] = 0.f;
    __syncthreads();
    for (int s = 256; s > 0; s >>= 1) {
        if (tid < s) red[tid] += red[tid + s];
        __syncthreads();
    }
    if (tid == 0) g_lpart[blockIdx.x] = red[0];
}

// ---------------------------------------------------------------------------
// Deterministic loss reduce in fp64: cl == cbl (identical forward values)
// ---------------------------------------------------------------------------
__global__ void k_loss(float* __restrict__ out) {
    if (threadIdx.x != 0 || blockIdx.x != 0) return;
    double s = 0.0;
    for (int i = 0; i < NBLK; i++) s += (double)g_lpart[i];
    const float v = (float)(s / 524288.0);   // per-stage mean over B*C*T, summed
    out[OFF_CL]     = v;
    out[OFF_CL + 1] = v;
}

// ---------------------------------------------------------------------------
extern "C" void kernel_launch(void* const* d_in, const int* in_sizes, int n_in,
                              void* d_out, int out_size) {
    (void)in_sizes; (void)n_in; (void)out_size;
    const float* z     = (const float*)d_in[0];
    const float* in_v  = (const float*)d_in[1];
    const float* in_g  = (const float*)d_in[2];
    const float* in_b  = (const float*)d_in[3];
    const float* out_v = (const float*)d_in[4];
    const float* out_g = (const float*)d_in[5];
    const float* out_b = (const float*)d_in[6];
    const float* cb    = (const float*)d_in[7];
    float* out = (float*)d_out;

    cudaFuncSetAttribute(k_mega, cudaFuncAttributeMaxDynamicSharedMemorySize, SMEM_TOT);

    kp_win  <<<72, 256>>>(in_v, in_g);
    kp_wout <<<(NCB*DD + 255)/256, 256>>>(out_v, out_g);
    kp_cb   <<<(NCB*KK + 255)/256, 256>>>(cb);

    k_mega <<<NBLK, THREADS, SMEM_TOT>>>(z, in_b, out_b, cb, out);
    k_loss <<<1, 32>>>(out);
}